// round 6
// baseline (speedup 1.0000x reference)
#include <cuda_runtime.h>

#define NR      96
#define DIM     768
#define TRIU    4560
#define P_CNT   9120
#define Q_CNT   9216
#define THR     0.3f
#define SPLITK  8              // 768/8 = 96 per split
#define NEG_SL  16
#define NEG_PER 576
#define POS_GR  9
#define HTHR    1024
#define HB      (NEG_SL * POS_GR)   // 144

// ---------------- device scratch ----------------
__device__ float g_partPos[SPLITK * P_CNT];
__device__ float g_partNeg[SPLITK * Q_CNT];
__device__ float g_partDiag[SPLITK * 2 * NR];
__device__ float g_blockSum[HB];
__device__ float g_posSum[POS_GR];
__device__ float g_negSum[NEG_SL];
__device__ unsigned g_count = 0;

// ---------------- helpers ----------------
__device__ __forceinline__ unsigned long long addx2(unsigned long long a,
                                                    unsigned long long b) {
    unsigned long long r;
    asm("add.rn.f32x2 %0, %1, %2;" : "=l"(r) : "l"(a), "l"(b));
    return r;
}
#define ABSMASK 0x7fffffff7fffffffULL

__device__ __forceinline__ int triu_base(int i) { return i * (191 - i) / 2; }
__device__ __forceinline__ int triu_idx(int i, int j) {
    return triu_base(i) + (j - i - 1);
}

__device__ __forceinline__ float blockReduce1024(float v, float* sbuf32) {
    __syncthreads();
    int t = threadIdx.x;
    #pragma unroll
    for (int o = 16; o; o >>= 1) v += __shfl_down_sync(0xffffffffu, v, o);
    if ((t & 31) == 0) sbuf32[t >> 5] = v;
    __syncthreads();
    float r = 0.f;
    if (t < 32) {
        r = sbuf32[t];
        #pragma unroll
        for (int o = 16; o; o >>= 1) r += __shfl_down_sync(0xffffffffu, r, o);
    }
    return r;   // valid at t == 0
}

// ---------------- K1: RAW grams + diag partials (168 blocks x 256) --------
__global__ void __launch_bounds__(256) k_gram(const float* __restrict__ S,
                                              const float* __restrict__ A) {
    __shared__ float As[32][34];
    __shared__ float Bs[32][34];

    int bx = blockIdx.x;
    int sk = bx / 21;
    int tl = bx % 21;

    int m, tr, tc;
    if (tl < 9) { m = 0; tr = tl / 3; tc = tl % 3; }
    else {
        int q = tl - 9;
        m = 1 + q / 6;
        const int TR6[6] = {0,0,0,1,1,2};
        const int TC6[6] = {0,1,2,1,2,2};
        tr = TR6[q % 6]; tc = TC6[q % 6];
    }
    // m0: neg = A x S^T; m1: S x S^T; m2: A x A^T
    const float* Ap = (m == 1) ? S : A;
    const float* Bp = (m == 2) ? A : S;

    int t  = threadIdx.x;
    int tx = t & 15, ty = t >> 4;

    float acc00 = 0.f, acc01 = 0.f, acc10 = 0.f, acc11 = 0.f;

    for (int ch = 0; ch < 3; ch++) {
        int kb = sk * 96 + ch * 32;
        __syncthreads();
        #pragma unroll
        for (int p = 0; p < 4; p++) {
            int lin = t + p * 256;
            int kk  = lin & 31, row = lin >> 5;
            As[kk][row] = Ap[(tr * 32 + row) * DIM + kb + kk];
            Bs[kk][row] = Bp[(tc * 32 + row) * DIM + kb + kk];
        }
        __syncthreads();
        #pragma unroll
        for (int kk = 0; kk < 32; kk++) {
            float2 a = *(const float2*)&As[kk][2 * ty];
            float2 b = *(const float2*)&Bs[kk][2 * tx];
            acc00 += a.x * b.x; acc01 += a.x * b.y;
            acc10 += a.y * b.x; acc11 += a.y * b.y;
        }
    }

    int r0 = tr * 32 + 2 * ty;
    int c0 = tc * 32 + 2 * tx;
    if (m == 0) {
        float* dst = g_partNeg + sk * Q_CNT;
        dst[r0 * 96 + c0]           = acc00;
        dst[r0 * 96 + c0 + 1]       = acc01;
        dst[(r0 + 1) * 96 + c0]     = acc10;
        dst[(r0 + 1) * 96 + c0 + 1] = acc11;
    } else {
        float* dst = g_partPos + sk * P_CNT + ((m == 2) ? TRIU : 0);
        if (r0     < c0    ) dst[triu_idx(r0,     c0    )] = acc00;
        if (r0     < c0 + 1) dst[triu_idx(r0,     c0 + 1)] = acc01;
        if (r0 + 1 < c0    ) dst[triu_idx(r0 + 1, c0    )] = acc10;
        if (r0 + 1 < c0 + 1) dst[triu_idx(r0 + 1, c0 + 1)] = acc11;
        if (r0 == c0) {  // diagonal entries -> squared row norms
            int off = (m == 1) ? 0 : NR;
            g_partDiag[sk * 2 * NR + off + r0]     = acc00;
            g_partDiag[sk * 2 * NR + off + r0 + 1] = acc11;
        }
    }
}

// ---------------- K2: normalize + hinge + fused final (144 x 1024) --------
__global__ void __launch_bounds__(HTHR, 1) k_hinge(float* __restrict__ out) {
    __shared__ __align__(16) float s_neg[NEG_PER];
    __shared__ float s_inv[2 * NR];
    __shared__ float sbuf[32];
    __shared__ bool s_last;

    int bid = blockIdx.x;
    int ns  = bid / POS_GR;       // 0..15
    int pg  = bid % POS_GR;       // 0..8
    int t   = threadIdx.x;

    // --- combine diag partials -> inverse norms (s_inv[0..95]=S, 96..191=A)
    if (t < 2 * NR) {
        float d = ((g_partDiag[0 * 192 + t] + g_partDiag[1 * 192 + t]) +
                   (g_partDiag[2 * 192 + t] + g_partDiag[3 * 192 + t])) +
                  ((g_partDiag[4 * 192 + t] + g_partDiag[5 * 192 + t]) +
                   (g_partDiag[6 * 192 + t] + g_partDiag[7 * 192 + t]));
        s_inv[t] = 1.0f / fmaxf(sqrtf(d), 1e-8f);
    }
    __syncthreads();

    // --- combine + normalize this block's neg slice into smem (+THR folded)
    int j0 = ns * NEG_PER;
    if (t < NEG_PER) {
        int gj = j0 + t;
        float raw = ((g_partNeg[0 * Q_CNT + gj] + g_partNeg[1 * Q_CNT + gj]) +
                     (g_partNeg[2 * Q_CNT + gj] + g_partNeg[3 * Q_CNT + gj])) +
                    ((g_partNeg[4 * Q_CNT + gj] + g_partNeg[5 * Q_CNT + gj]) +
                     (g_partNeg[6 * Q_CNT + gj] + g_partNeg[7 * Q_CNT + gj]));
        int r = gj / 96, c = gj % 96;
        s_neg[t] = raw * s_inv[NR + r] * s_inv[c] + THR;
    }

    // --- combine + normalize this thread's pos value
    int pid = pg * HTHR + t;
    bool act = (pid < P_CNT);
    float posv = 0.f;
    if (act) {
        float raw = ((g_partPos[0 * P_CNT + pid] + g_partPos[1 * P_CNT + pid]) +
                     (g_partPos[2 * P_CNT + pid] + g_partPos[3 * P_CNT + pid])) +
                    ((g_partPos[4 * P_CNT + pid] + g_partPos[5 * P_CNT + pid]) +
                     (g_partPos[6 * P_CNT + pid] + g_partPos[7 * P_CNT + pid]));
        int invo = (pid < TRIU) ? 0 : NR;
        int p    = (pid < TRIU) ? pid : (pid - TRIU);
        int i = (int)((191.0 - sqrt(36481.0 - 8.0 * (double)p)) * 0.5);
        while (triu_base(i + 1) <= p) ++i;
        while (triu_base(i) > p)      --i;
        int j = p - triu_base(i) + i + 1;
        posv = raw * s_inv[invo + i] * s_inv[invo + j];
    }
    __syncthreads();

    // --- designated blocks record separable sums
    if (ns == 0) {
        float r = blockReduce1024(act ? posv : 0.f, sbuf);
        if (t == 0) g_posSum[pg] = r;
    }
    if (pg == 0) {
        // s_neg holds n+THR; subtract THR back for the pure neg sum
        float v = (t < NEG_PER) ? (s_neg[t] - THR) : 0.f;
        float r = blockReduce1024(v, sbuf);
        if (t == 0) g_negSum[ns] = r;
    }

    // --- main hinge: sum |(n+thr) - p|, packed f32x2, 8 chains, batched LDS
    float acc = 0.f;
    if (act) {
        float cc = -posv;
        unsigned cu = __float_as_uint(cc);
        unsigned long long c2 = ((unsigned long long)cu << 32) | cu;
        const ulonglong2* sn = reinterpret_cast<const ulonglong2*>(s_neg); // 144
        unsigned long long a0 = 0ull, a1 = 0ull, a2 = 0ull, a3 = 0ull;
        unsigned long long a4 = 0ull, a5 = 0ull, a6 = 0ull, a7 = 0ull;
        #pragma unroll 4
        for (int i = 0; i < NEG_PER / 4; i += 4) {   // 36 iters, 16 negs each
            ulonglong2 v0 = sn[i];
            ulonglong2 v1 = sn[i + 1];
            ulonglong2 v2 = sn[i + 2];
            ulonglong2 v3 = sn[i + 3];
            a0 = addx2(a0, addx2(v0.x, c2) & ABSMASK);
            a1 = addx2(a1, addx2(v0.y, c2) & ABSMASK);
            a2 = addx2(a2, addx2(v1.x, c2) & ABSMASK);
            a3 = addx2(a3, addx2(v1.y, c2) & ABSMASK);
            a4 = addx2(a4, addx2(v2.x, c2) & ABSMASK);
            a5 = addx2(a5, addx2(v2.y, c2) & ABSMASK);
            a6 = addx2(a6, addx2(v3.x, c2) & ABSMASK);
            a7 = addx2(a7, addx2(v3.y, c2) & ABSMASK);
        }
        a0 = addx2(addx2(a0, a1), addx2(a2, a3));
        a4 = addx2(addx2(a4, a5), addx2(a6, a7));
        a0 = addx2(a0, a4);
        acc = __uint_as_float((unsigned)a0) + __uint_as_float((unsigned)(a0 >> 32));
    }
    float bsum = blockReduce1024(acc, sbuf);
    if (t == 0) g_blockSum[bid] = bsum;

    // --- last-block-done deterministic final combine
    if (t == 0) {
        __threadfence();
        unsigned old = atomicInc(&g_count, HB - 1);
        s_last = (old == HB - 1);
    }
    __syncthreads();
    if (!s_last) return;
    __threadfence();

    float vA = (t < HB)     ? g_blockSum[t] : 0.f;
    float S_abs = blockReduce1024(vA, sbuf);
    float vP = (t < POS_GR) ? g_posSum[t]   : 0.f;
    float S_pos = blockReduce1024(vP, sbuf);
    float vN = (t < NEG_SL) ? g_negSum[t]   : 0.f;
    float S_neg = blockReduce1024(vN, sbuf);

    if (t == 0) {
        const double P = (double)P_CNT, Q = (double)Q_CNT, thr = (double)THR;
        double Sx = P * (double)S_neg - Q * (double)S_pos + P * Q * thr;
        out[0] = (float)(0.5 * (Sx + (double)S_abs) / (P * Q));
    }
}

// ---------------- launch ----------------
extern "C" void kernel_launch(void* const* d_in, const int* in_sizes, int n_in,
                              void* d_out, int out_size) {
    const float* stereos  = (const float*)d_in[0];
    const float* astereos = (const float*)d_in[1];
    k_gram<<<21 * SPLITK, 256>>>(stereos, astereos);
    k_hinge<<<HB, HTHR>>>((float*)d_out);
}